// round 10
// baseline (speedup 1.0000x reference)
#include <cuda_runtime.h>
#include <cuda_bf16.h>
#include <cstdint>

#define BB 16
#define SS 2048
#define DD 64
#define TQ 128
#define NJ 128
#define NT 256
#define NTILES (SS / NJ)

// dynamic smem: Q hi/lo (32KB) + two K/V buffers (64KB each)
#define OQH 0
#define OQL 16384
#define OKV 32768
#define KVBUF 65536
#define SMEM_DYN (32768 + 2 * KVBUF + 1024)

#define SWZ(o) ((o) ^ (((o) >> 3) & 0x70u))

static __device__ __forceinline__ uint32_t packbf(float lo, float hi) {
    uint32_t r;
    asm("cvt.rn.bf16x2.f32 %0, %1, %2;" : "=r"(r) : "f"(hi), "f"(lo));
    return r;
}
static __device__ __forceinline__ float ubf(uint32_t u) { return __uint_as_float(u); }

static __device__ __forceinline__ void ldsm4(uint32_t* r, uint32_t a) {
    asm volatile("ldmatrix.sync.aligned.m8n8.x4.shared.b16 {%0,%1,%2,%3}, [%4];"
        : "=r"(r[0]), "=r"(r[1]), "=r"(r[2]), "=r"(r[3]) : "r"(a));
}
static __device__ __forceinline__ void ldsm4t(uint32_t* r, uint32_t a) {
    asm volatile("ldmatrix.sync.aligned.m8n8.x4.trans.shared.b16 {%0,%1,%2,%3}, [%4];"
        : "=r"(r[0]), "=r"(r[1]), "=r"(r[2]), "=r"(r[3]) : "r"(a));
}
static __device__ __forceinline__ void mma16816(float* c, const uint32_t* a,
                                                uint32_t b0, uint32_t b1) {
    asm volatile("mma.sync.aligned.m16n8k16.row.col.f32.bf16.bf16.f32 "
        "{%0,%1,%2,%3}, {%4,%5,%6,%7}, {%8,%9}, {%0,%1,%2,%3};"
        : "+f"(c[0]), "+f"(c[1]), "+f"(c[2]), "+f"(c[3])
        : "r"(a[0]), "r"(a[1]), "r"(a[2]), "r"(a[3]), "r"(b0), "r"(b1));
}
static __device__ __forceinline__ uint32_t s2u(const void* p) {
    uint32_t a;
    asm("{ .reg .u64 t; cvta.to.shared.u64 t, %1; cvt.u32.u64 %0, t; }" : "=r"(a) : "l"(p));
    return a;
}
static __device__ __forceinline__ uint32_t b2b(uint32_t wv, int sh) {
    uint32_t r = 0;
    r |= ((wv & 0x000000FFu) ? 1u : 0u) << sh;
    r |= ((wv & 0x0000FF00u) ? 1u : 0u) << (sh + 1);
    r |= ((wv & 0x00FF0000u) ? 1u : 0u) << (sh + 2);
    r |= ((wv & 0xFF000000u) ? 1u : 0u) << (sh + 3);
    return r;
}

// stage a [128 x 64] fp32 tile as bf16 hi/lo into SW128 smem (prologue path)
static __device__ __forceinline__ void stage_bf(const float* __restrict__ g,
                                                char* sh, char* sl, float sc, int tid)
{
    for (int i = tid; i < 1024; i += NT) {
        int row = i >> 3, c8 = (i & 7) << 3;
        float4 a = *(const float4*)(g + row * 64 + c8);
        float4 b = *(const float4*)(g + row * 64 + c8 + 4);
        float y[8] = {a.x*sc, a.y*sc, a.z*sc, a.w*sc, b.x*sc, b.y*sc, b.z*sc, b.w*sc};
        uint32_t h[4], l[4];
#pragma unroll
        for (int p = 0; p < 4; p++) {
            h[p] = packbf(y[2*p], y[2*p+1]);
            float f0 = ubf(h[p] << 16), f1 = ubf(h[p] & 0xFFFF0000u);
            l[p] = packbf(y[2*p] - f0, y[2*p+1] - f1);
        }
        uint32_t off = SWZ((uint32_t)(row * 128 + c8 * 2));
        *(uint4*)(sh + off) = make_uint4(h[0], h[1], h[2], h[3]);
        *(uint4*)(sl + off) = make_uint4(l[0], l[1], l[2], l[3]);
    }
}

// pipelined staging: gmem -> regs, later regs -> smem (bf16 hi/lo)
static __device__ __forceinline__ void pf_load(const float* __restrict__ g,
                                               float4* pf, int tid)
{
#pragma unroll
    for (int it = 0; it < 4; it++) {
        int i = it * NT + tid;
        int row = i >> 3, c8 = (i & 7) << 3;
        pf[2*it]   = *(const float4*)(g + row * 64 + c8);
        pf[2*it+1] = *(const float4*)(g + row * 64 + c8 + 4);
    }
}
static __device__ __forceinline__ void pf_store(const float4* pf,
                                                char* sh, char* sl, int tid)
{
#pragma unroll
    for (int it = 0; it < 4; it++) {
        int i = it * NT + tid;
        int row = i >> 3, c8 = (i & 7) << 3;
        float4 a = pf[2*it], b = pf[2*it+1];
        float y[8] = {a.x, a.y, a.z, a.w, b.x, b.y, b.z, b.w};
        uint32_t h[4], l[4];
#pragma unroll
        for (int p = 0; p < 4; p++) {
            h[p] = packbf(y[2*p], y[2*p+1]);
            float f0 = ubf(h[p] << 16), f1 = ubf(h[p] & 0xFFFF0000u);
            l[p] = packbf(y[2*p] - f0, y[2*p+1] - f1);
        }
        uint32_t off = SWZ((uint32_t)(row * 128 + c8 * 2));
        *(uint4*)(sh + off) = make_uint4(h[0], h[1], h[2], h[3]);
        *(uint4*)(sl + off) = make_uint4(l[0], l[1], l[2], l[3]);
    }
}

__global__ __launch_bounds__(NT) void sdpa_mma_kernel(
    const float* __restrict__ q, const float* __restrict__ k,
    const float* __restrict__ v, const void* __restrict__ maskp,
    float* __restrict__ out, float* __restrict__ attn)
{
    const int b   = blockIdx.y;
    const int q0  = blockIdx.x * TQ;
    const int tid = threadIdx.x;
    const int w   = tid >> 5;
    const int lid = tid & 31;
    const int g   = lid >> 2;
    const int t2  = lid & 3;
    const int bq  = b * SS + q0;

    extern __shared__ char dsm_raw[];
    char* dsm = (char*)(((uintptr_t)dsm_raw + 1023) & ~(uintptr_t)1023);
    const uint32_t uQH = s2u(dsm + OQH), uQL = s2u(dsm + OQL);
    const uint32_t uKV = s2u(dsm + OKV);

    const float* qb = q + ((size_t)bq) * DD;
    const float* kb = k + (size_t)b * SS * DD;
    const float* vb = v + (size_t)b * SS * DD;
    const unsigned char* m8b  = (const unsigned char*)maskp + (size_t)b * SS * SS;
    const uint32_t*      m32b = (const uint32_t*)maskp + (size_t)b * SS * SS;

    // ---- fused mask-dtype detect: scan 1024 words of this CTA's own slice ----
    int pF = 0, pB = 0;
    {
        uint4 u = *((const uint4*)(m32b + (size_t)q0 * SS) + tid);
        uint32_t ws[4] = {u.x, u.y, u.z, u.w};
#pragma unroll
        for (int i = 0; i < 4; i++) {
            if (ws[i] == 0x3F800000u) pF = 1;
            else if (ws[i] > 1u)      pB = 1;
        }
    }

    // ---- prologue staging: Q (scaled by 1/8), K/V tile0 into buffer 0 ----
    stage_bf(qb, dsm + OQH, dsm + OQL, 0.125f, tid);
    stage_bf(kb, dsm + OKV,         dsm + OKV + 16384, 1.0f, tid);
    stage_bf(vb, dsm + OKV + 32768, dsm + OKV + 49152, 1.0f, tid);

    const int anyF = __syncthreads_or(pF);
    const int anyB = __syncthreads_or(pB);
    const int mk = anyF ? 2 : (anyB ? 0 : 1);   // 0=uint8, 1=int32, 2=float32

    // ldmatrix lane address patterns
    const int krow = (lid & 7) + ((lid >> 4) & 1) * 8;
    const int kbyt = ((lid >> 3) & 1) * 16;
    const int qrow = (lid & 7) + ((lid >> 3) & 1) * 8;
    const int qbyt = ((lid >> 4) & 1) * 16;

    float OD[8][4];
#pragma unroll
    for (int i = 0; i < 8; i++)
#pragma unroll
        for (int jx = 0; jx < 4; jx++) OD[i][jx] = 0.f;

    float rs0 = 0.f, rs1 = 0.f;

    for (int t = 0; t < NTILES; t++) {
        const int j0 = t * NJ;
        const uint32_t kvo  = (uint32_t)((t & 1) * KVBUF);
        const uint32_t nkvo = kvo ^ KVBUF;
        const uint32_t uKH = uKV + kvo, uKL = uKH + 16384;
        const uint32_t uVH = uKH + 32768, uVL = uKH + 49152;
        const bool more = (t + 1 < NTILES);

        // prefetch next K tile (hidden behind GEMM1)
        float4 pfK[8];
        if (more) pf_load(kb + (size_t)(j0 + NJ) * DD, pfK, tid);

        // ---------------- GEMM1: C = Q x K^T, 3-term bf16 split ----------------
        float C[16][4];
#pragma unroll
        for (int fn = 0; fn < 16; fn++)
#pragma unroll
            for (int jx = 0; jx < 4; jx++) C[fn][jx] = 0.f;

#pragma unroll
        for (int ks = 0; ks < 4; ks++) {
            uint32_t qh[4], ql[4];
            uint32_t qoff = (uint32_t)(w * 2048 +
                (((qrow * 128) | (ks * 32) | qbyt) ^ ((qrow & 7) << 4)));
            ldsm4(qh, uQH + qoff);
            ldsm4(ql, uQL + qoff);
#pragma unroll
            for (int jg = 0; jg < 8; jg++) {
                uint32_t kh[4], kl[4];
                uint32_t koff = (uint32_t)(jg * 2048 +
                    (((krow * 128) | (ks * 32) | kbyt) ^ ((krow & 7) << 4)));
                ldsm4(kh, uKH + koff);
                ldsm4(kl, uKL + koff);
                mma16816(C[2*jg],   qh, kh[0], kh[1]);
                mma16816(C[2*jg+1], qh, kh[2], kh[3]);
                mma16816(C[2*jg],   qh, kl[0], kl[1]);
                mma16816(C[2*jg+1], qh, kl[2], kl[3]);
                mma16816(C[2*jg],   ql, kh[0], kh[1]);
                mma16816(C[2*jg+1], ql, kh[2], kh[3]);
            }
        }

        // stash next K into the idle buffer (frees pfK regs)
        if (more) pf_store(pfK, dsm + OKV + nkvo, dsm + OKV + nkvo + 16384, tid);

        // ---------------- mask bits: per-quad gmem loads + shfl ----------------
        uint32_t myb0 = 0, myb1 = 0;
        {
            const size_t mrow0 = (size_t)(q0 + w * 16 + g) * SS + j0 + t2 * 32;
            if (mk == 0) {
                const uint4* p0 = (const uint4*)(m8b + mrow0);
                const uint4* p1 = (const uint4*)(m8b + mrow0 + (size_t)8 * SS);
                uint4 x0 = p0[0], y0 = p0[1], x1 = p1[0], y1 = p1[1];
                myb0 = b2b(x0.x,0)|b2b(x0.y,4)|b2b(x0.z,8)|b2b(x0.w,12)
                     | b2b(y0.x,16)|b2b(y0.y,20)|b2b(y0.z,24)|b2b(y0.w,28);
                myb1 = b2b(x1.x,0)|b2b(x1.y,4)|b2b(x1.z,8)|b2b(x1.w,12)
                     | b2b(y1.x,16)|b2b(y1.y,20)|b2b(y1.z,24)|b2b(y1.w,28);
            } else {
                const uint4* p0 = (const uint4*)(m32b + mrow0);
                const uint4* p1 = (const uint4*)(m32b + mrow0 + (size_t)8 * SS);
#pragma unroll
                for (int ii = 0; ii < 8; ii++) {
                    uint4 a = p0[ii];
                    myb0 |= (a.x?1u:0u)<<(ii*4)   | (a.y?1u:0u)<<(ii*4+1)
                          | (a.z?1u:0u)<<(ii*4+2) | (a.w?1u:0u)<<(ii*4+3);
                    uint4 c = p1[ii];
                    myb1 |= (c.x?1u:0u)<<(ii*4)   | (c.y?1u:0u)<<(ii*4+1)
                          | (c.z?1u:0u)<<(ii*4+2) | (c.w?1u:0u)<<(ii*4+3);
                }
            }
        }
        uint32_t mw0[4], mw1[4];
#pragma unroll
        for (int i = 0; i < 4; i++) {
            mw0[i] = __shfl_sync(0xffffffffu, myb0, (lid & ~3) | i);
            mw1[i] = __shfl_sync(0xffffffffu, myb1, (lid & ~3) | i);
        }

        // ---------------- epilogue: exp, rowsum, raw attn, C->P frags ----------------
        float* ar0 = attn + ((size_t)(bq + w * 16 + g)) * SS + j0;
        float* ar1 = ar0 + (size_t)8 * SS;

        uint32_t phi[8][4], plo[8][4];
#pragma unroll
        for (int fn = 0; fn < 16; fn++) {
            int sh = (fn & 3) * 8 + t2 * 2;
            uint32_t w0 = mw0[fn >> 2], w1 = mw1[fn >> 2];
            float p0 = ((w0 >> sh) & 1u)       ? 0.f : __expf(C[fn][0]);
            float p1 = ((w0 >> (sh + 1)) & 1u) ? 0.f : __expf(C[fn][1]);
            float p2 = ((w1 >> sh) & 1u)       ? 0.f : __expf(C[fn][2]);
            float p3 = ((w1 >> (sh + 1)) & 1u) ? 0.f : __expf(C[fn][3]);
            rs0 += p0 + p1;
            rs1 += p2 + p3;
            *(float2*)(ar0 + fn * 8 + t2 * 2) = make_float2(p0, p1);
            *(float2*)(ar1 + fn * 8 + t2 * 2) = make_float2(p2, p3);

            uint32_t h01 = packbf(p0, p1), h23 = packbf(p2, p3);
            float f0 = ubf(h01 << 16), f1 = ubf(h01 & 0xFFFF0000u);
            float f2 = ubf(h23 << 16), f3 = ubf(h23 & 0xFFFF0000u);
            uint32_t l01 = packbf(p0 - f0, p1 - f1);
            uint32_t l23 = packbf(p2 - f2, p3 - f3);
            int k2 = fn >> 1, o = (fn & 1) * 2;
            phi[k2][o] = h01; phi[k2][o + 1] = h23;
            plo[k2][o] = l01; plo[k2][o + 1] = l23;
        }

        // prefetch next V tile (hidden behind GEMM2)
        float4 pfV[8];
        if (more) pf_load(vb + (size_t)(j0 + NJ) * DD, pfV, tid);

        // ---------------- GEMM2: OD += P x V, 3-term split ----------------
#pragma unroll
        for (int ks2 = 0; ks2 < 8; ks2++) {
#pragma unroll
            for (int dg = 0; dg < 4; dg++) {
                uint32_t vh[4], vl[4];
                uint32_t voff = (uint32_t)(ks2 * 2048 +
                    (((qrow * 128) | (dg * 32) | qbyt) ^ ((qrow & 7) << 4)));
                ldsm4t(vh, uVH + voff);
                ldsm4t(vl, uVL + voff);
                mma16816(OD[2*dg],   phi[ks2], vh[0], vh[1]);
                mma16816(OD[2*dg+1], phi[ks2], vh[2], vh[3]);
                mma16816(OD[2*dg],   phi[ks2], vl[0], vl[1]);
                mma16816(OD[2*dg+1], phi[ks2], vl[2], vl[3]);
                mma16816(OD[2*dg],   plo[ks2], vh[0], vh[1]);
                mma16816(OD[2*dg+1], plo[ks2], vh[2], vh[3]);
            }
        }

        if (more) pf_store(pfV, dsm + OKV + nkvo + 32768, dsm + OKV + nkvo + 49152, tid);
        __syncthreads();
    }

    // ---- row sums: quad-reduce (lanes in a quad share rows) ----
    rs0 += __shfl_xor_sync(0xffffffffu, rs0, 1);
    rs0 += __shfl_xor_sync(0xffffffffu, rs0, 2);
    rs1 += __shfl_xor_sync(0xffffffffu, rs1, 1);
    rs1 += __shfl_xor_sync(0xffffffffu, rs1, 2);
    const float inv0 = 1.0f / rs0, inv1 = 1.0f / rs1;

    // ---- output: scale PV accumulators ----
    float* o0 = out + (size_t)(bq + w * 16 + g) * DD;
    float* o1 = o0 + (size_t)8 * DD;
#pragma unroll
    for (int dn = 0; dn < 8; dn++) {
        *(float2*)(o0 + dn * 8 + t2 * 2) = make_float2(OD[dn][0] * inv0, OD[dn][1] * inv0);
        *(float2*)(o1 + dn * 8 + t2 * 2) = make_float2(OD[dn][2] * inv1, OD[dn][3] * inv1);
    }

    // ---- fused attn normalization: each quad rescales its own two rows ----
    __syncthreads();   // all raw-p writes by this CTA visible to all its threads
    float4* r0p = (float4*)(attn + (size_t)(bq + w * 16 + g) * SS);
    float4* r1p = (float4*)(attn + (size_t)(bq + w * 16 + 8 + g) * SS);
#pragma unroll 4
    for (int j4 = t2; j4 < SS / 4; j4 += 4) {
        float4 a = r0p[j4];
        a.x *= inv0; a.y *= inv0; a.z *= inv0; a.w *= inv0;
        r0p[j4] = a;
        float4 c = r1p[j4];
        c.x *= inv1; c.y *= inv1; c.z *= inv1; c.w *= inv1;
        r1p[j4] = c;
    }
}

extern "C" void kernel_launch(void* const* d_in, const int* in_sizes, int n_in,
                              void* d_out, int out_size)
{
    const float* q = (const float*)d_in[0];
    const float* k = (const float*)d_in[1];
    const float* v = (const float*)d_in[2];
    const void*  mask = d_in[3];

    float* out  = (float*)d_out;
    float* attn = out + (size_t)BB * SS * DD;   // tuple order: (output, attn)

    cudaFuncSetAttribute(sdpa_mma_kernel,
                         cudaFuncAttributeMaxDynamicSharedMemorySize, SMEM_DYN);

    dim3 grid(SS / TQ, BB);
    sdpa_mma_kernel<<<grid, NT, SMEM_DYN>>>(q, k, v, mask, out, attn);
}

// round 11
// speedup vs baseline: 1.2532x; 1.2532x over previous
#include <cuda_runtime.h>
#include <cuda_bf16.h>
#include <cstdint>

#define BB 16
#define SS 2048
#define DD 64
#define TQ 128
#define NJ 128
#define NT 256
#define NTILES (SS / NJ)

// dynamic smem: Q hi/lo (32KB) + single K/V buffer (64KB)
#define OQH 0
#define OQL 16384
#define OKH 32768
#define OKL 49152
#define OVH 65536
#define OVL 81920
#define SMEM_DYN (98304 + 1024)

#define SWZ(o) ((o) ^ (((o) >> 3) & 0x70u))

static __device__ __forceinline__ uint32_t packbf(float lo, float hi) {
    uint32_t r;
    asm("cvt.rn.bf16x2.f32 %0, %1, %2;" : "=r"(r) : "f"(hi), "f"(lo));
    return r;
}
static __device__ __forceinline__ float ubf(uint32_t u) { return __uint_as_float(u); }

static __device__ __forceinline__ void ldsm4(uint32_t* r, uint32_t a) {
    asm volatile("ldmatrix.sync.aligned.m8n8.x4.shared.b16 {%0,%1,%2,%3}, [%4];"
        : "=r"(r[0]), "=r"(r[1]), "=r"(r[2]), "=r"(r[3]) : "r"(a));
}
static __device__ __forceinline__ void ldsm4t(uint32_t* r, uint32_t a) {
    asm volatile("ldmatrix.sync.aligned.m8n8.x4.trans.shared.b16 {%0,%1,%2,%3}, [%4];"
        : "=r"(r[0]), "=r"(r[1]), "=r"(r[2]), "=r"(r[3]) : "r"(a));
}
static __device__ __forceinline__ void mma16816(float* c, const uint32_t* a,
                                                uint32_t b0, uint32_t b1) {
    asm volatile("mma.sync.aligned.m16n8k16.row.col.f32.bf16.bf16.f32 "
        "{%0,%1,%2,%3}, {%4,%5,%6,%7}, {%8,%9}, {%0,%1,%2,%3};"
        : "+f"(c[0]), "+f"(c[1]), "+f"(c[2]), "+f"(c[3])
        : "r"(a[0]), "r"(a[1]), "r"(a[2]), "r"(a[3]), "r"(b0), "r"(b1));
}
static __device__ __forceinline__ uint32_t s2u(const void* p) {
    uint32_t a;
    asm("{ .reg .u64 t; cvta.to.shared.u64 t, %1; cvt.u32.u64 %0, t; }" : "=r"(a) : "l"(p));
    return a;
}
static __device__ __forceinline__ uint32_t b2b(uint32_t wv, int sh) {
    uint32_t r = 0;
    r |= ((wv & 0x000000FFu) ? 1u : 0u) << sh;
    r |= ((wv & 0x0000FF00u) ? 1u : 0u) << (sh + 1);
    r |= ((wv & 0x00FF0000u) ? 1u : 0u) << (sh + 2);
    r |= ((wv & 0xFF000000u) ? 1u : 0u) << (sh + 3);
    return r;
}

// stage a [128 x 64] fp32 tile as bf16 hi/lo into SW128 smem
static __device__ __forceinline__ void stage_bf(const float* __restrict__ g,
                                                char* sh, char* sl, float sc, int tid)
{
#pragma unroll
    for (int it = 0; it < 4; it++) {
        int i = it * NT + tid;
        int row = i >> 3, c8 = (i & 7) << 3;
        float4 a = *(const float4*)(g + row * 64 + c8);
        float4 b = *(const float4*)(g + row * 64 + c8 + 4);
        float y[8] = {a.x*sc, a.y*sc, a.z*sc, a.w*sc, b.x*sc, b.y*sc, b.z*sc, b.w*sc};
        uint32_t h[4], l[4];
#pragma unroll
        for (int p = 0; p < 4; p++) {
            h[p] = packbf(y[2*p], y[2*p+1]);
            float f0 = ubf(h[p] << 16), f1 = ubf(h[p] & 0xFFFF0000u);
            l[p] = packbf(y[2*p] - f0, y[2*p+1] - f1);
        }
        uint32_t off = SWZ((uint32_t)(row * 128 + c8 * 2));
        *(uint4*)(sh + off) = make_uint4(h[0], h[1], h[2], h[3]);
        *(uint4*)(sl + off) = make_uint4(l[0], l[1], l[2], l[3]);
    }
}

__global__ __launch_bounds__(NT, 2) void sdpa_mma_kernel(
    const float* __restrict__ q, const float* __restrict__ k,
    const float* __restrict__ v, const void* __restrict__ maskp,
    float* __restrict__ out, float* __restrict__ attn)
{
    const int b   = blockIdx.y;
    const int q0  = blockIdx.x * TQ;
    const int tid = threadIdx.x;
    const int w   = tid >> 5;
    const int lid = tid & 31;
    const int g   = lid >> 2;
    const int t2  = lid & 3;
    const int bq  = b * SS + q0;

    extern __shared__ char dsm_raw[];
    char* dsm = (char*)(((uintptr_t)dsm_raw + 1023) & ~(uintptr_t)1023);
    const uint32_t uQH = s2u(dsm + OQH), uQL = s2u(dsm + OQL);
    const uint32_t uKH = s2u(dsm + OKH), uKL = s2u(dsm + OKL);
    const uint32_t uVH = s2u(dsm + OVH), uVL = s2u(dsm + OVL);

    const float* qb = q + ((size_t)bq) * DD;
    const float* kb = k + (size_t)b * SS * DD;
    const float* vb = v + (size_t)b * SS * DD;
    const unsigned char* m8b  = (const unsigned char*)maskp + (size_t)b * SS * SS;
    const uint32_t*      m32b = (const uint32_t*)maskp + (size_t)b * SS * SS;

    // ---- fused mask-dtype detect over this CTA's own slice ----
    int pF = 0, pB = 0;
    {
        uint4 u = *((const uint4*)(m32b + (size_t)q0 * SS) + tid);
        uint32_t ws[4] = {u.x, u.y, u.z, u.w};
#pragma unroll
        for (int i = 0; i < 4; i++) {
            if (ws[i] == 0x3F800000u) pF = 1;
            else if (ws[i] > 1u)      pB = 1;
        }
    }

    // Q staged once, pre-scaled by 1/sqrt(64)
    stage_bf(qb, dsm + OQH, dsm + OQL, 0.125f, tid);

    const int anyF = __syncthreads_or(pF);
    const int anyB = __syncthreads_or(pB);
    const int mk = anyF ? 2 : (anyB ? 0 : 1);   // 0=uint8, 1=int32, 2=float32

    // ldmatrix lane address patterns
    const int krow = (lid & 7) + ((lid >> 4) & 1) * 8;
    const int kbyt = ((lid >> 3) & 1) * 16;
    const int qrow = (lid & 7) + ((lid >> 3) & 1) * 8;
    const int qbyt = ((lid >> 4) & 1) * 16;

    float OD[8][4];
#pragma unroll
    for (int i = 0; i < 8; i++)
#pragma unroll
        for (int jx = 0; jx < 4; jx++) OD[i][jx] = 0.f;

    float rs0 = 0.f, rs1 = 0.f;

    for (int t = 0; t < NTILES; t++) {
        const int j0 = t * NJ;

        if (t > 0) __syncthreads();           // prior tile's GEMM2 done reading
        stage_bf(kb + (size_t)j0 * DD, dsm + OKH, dsm + OKL, 1.0f, tid);
        stage_bf(vb + (size_t)j0 * DD, dsm + OVH, dsm + OVL, 1.0f, tid);
        __syncthreads();

        // ---- mask bits for this tile: per-quad loads + shfl (no smem) ----
        uint32_t myb0 = 0, myb1 = 0;
        {
            const size_t mrow0 = (size_t)(q0 + w * 16 + g) * SS + j0 + t2 * 32;
            if (mk == 0) {
                const uint4* p0 = (const uint4*)(m8b + mrow0);
                const uint4* p1 = (const uint4*)(m8b + mrow0 + (size_t)8 * SS);
                uint4 x0 = p0[0], y0 = p0[1], x1 = p1[0], y1 = p1[1];
                myb0 = b2b(x0.x,0)|b2b(x0.y,4)|b2b(x0.z,8)|b2b(x0.w,12)
                     | b2b(y0.x,16)|b2b(y0.y,20)|b2b(y0.z,24)|b2b(y0.w,28);
                myb1 = b2b(x1.x,0)|b2b(x1.y,4)|b2b(x1.z,8)|b2b(x1.w,12)
                     | b2b(y1.x,16)|b2b(y1.y,20)|b2b(y1.z,24)|b2b(y1.w,28);
            } else {
                const uint4* p0 = (const uint4*)(m32b + mrow0);
                const uint4* p1 = (const uint4*)(m32b + mrow0 + (size_t)8 * SS);
#pragma unroll
                for (int ii = 0; ii < 8; ii++) {
                    uint4 a = p0[ii];
                    myb0 |= (a.x?1u:0u)<<(ii*4)   | (a.y?1u:0u)<<(ii*4+1)
                          | (a.z?1u:0u)<<(ii*4+2) | (a.w?1u:0u)<<(ii*4+3);
                    uint4 c = p1[ii];
                    myb1 |= (c.x?1u:0u)<<(ii*4)   | (c.y?1u:0u)<<(ii*4+1)
                          | (c.z?1u:0u)<<(ii*4+2) | (c.w?1u:0u)<<(ii*4+3);
                }
            }
        }
        uint32_t mw0[4], mw1[4];
#pragma unroll
        for (int i = 0; i < 4; i++) {
            mw0[i] = __shfl_sync(0xffffffffu, myb0, (lid & ~3) | i);
            mw1[i] = __shfl_sync(0xffffffffu, myb1, (lid & ~3) | i);
        }

        float* ar0 = attn + ((size_t)(bq + w * 16 + g)) * SS + j0;
        float* ar1 = ar0 + (size_t)8 * SS;

        // ---- two jg-halves: GEMM1(4 slabs) then per-slab epilogue + GEMM2 ----
#pragma unroll
        for (int hf = 0; hf < 2; hf++) {
            float C[8][4];
#pragma unroll
            for (int fn = 0; fn < 8; fn++)
#pragma unroll
                for (int jx = 0; jx < 4; jx++) C[fn][jx] = 0.f;

#pragma unroll
            for (int ks = 0; ks < 4; ks++) {
                uint32_t qh[4], ql[4];
                uint32_t qoff = (uint32_t)(w * 2048 +
                    (((qrow * 128) | (ks * 32) | qbyt) ^ ((qrow & 7) << 4)));
                ldsm4(qh, uQH + qoff);
                ldsm4(ql, uQL + qoff);
#pragma unroll
                for (int jj = 0; jj < 4; jj++) {
                    const int jg = hf * 4 + jj;
                    uint32_t kh[4], kl[4];
                    uint32_t koff = (uint32_t)(jg * 2048 +
                        (((krow * 128) | (ks * 32) | kbyt) ^ ((krow & 7) << 4)));
                    ldsm4(kh, uKH + koff);
                    ldsm4(kl, uKL + koff);
                    mma16816(C[2*jj],   qh, kh[0], kh[1]);
                    mma16816(C[2*jj+1], qh, kh[2], kh[3]);
                    mma16816(C[2*jj],   qh, kl[0], kl[1]);
                    mma16816(C[2*jj+1], qh, kl[2], kl[3]);
                    mma16816(C[2*jj],   ql, kh[0], kh[1]);
                    mma16816(C[2*jj+1], ql, kh[2], kh[3]);
                }
            }

            // per-slab: mask/exp/rowsum/attn-store -> P frags -> PV MMAs
#pragma unroll
            for (int jj = 0; jj < 4; jj++) {
                const int jg = hf * 4 + jj;
                uint32_t phi[4], plo[4];
#pragma unroll
                for (int fo = 0; fo < 2; fo++) {
                    const int fn = 2 * jg + fo;
                    int sh = (fn & 3) * 8 + t2 * 2;
                    uint32_t w0 = mw0[fn >> 2], w1 = mw1[fn >> 2];
                    float* Cf = C[2*jj + fo];
                    float p0 = ((w0 >> sh) & 1u)       ? 0.f : __expf(Cf[0]);
                    float p1 = ((w0 >> (sh + 1)) & 1u) ? 0.f : __expf(Cf[1]);
                    float p2 = ((w1 >> sh) & 1u)       ? 0.f : __expf(Cf[2]);
                    float p3 = ((w1 >> (sh + 1)) & 1u) ? 0.f : __expf(Cf[3]);
                    rs0 += p0 + p1;
                    rs1 += p2 + p3;
                    *(float2*)(ar0 + fn * 8 + t2 * 2) = make_float2(p0, p1);
                    *(float2*)(ar1 + fn * 8 + t2 * 2) = make_float2(p2, p3);

                    uint32_t h01 = packbf(p0, p1), h23 = packbf(p2, p3);
                    float f0 = ubf(h01 << 16), f1 = ubf(h01 & 0xFFFF0000u);
                    float f2 = ubf(h23 << 16), f3 = ubf(h23 & 0xFFFF0000u);
                    int o = fo * 2;
                    phi[o] = h01; phi[o + 1] = h23;
                    plo[o] = packbf(p0 - f0, p1 - f1);
                    plo[o + 1] = packbf(p2 - f2, p3 - f3);
                }
#pragma unroll
                for (int dg = 0; dg < 4; dg++) {
                    uint32_t vh[4], vl[4];
                    uint32_t voff = (uint32_t)(jg * 2048 +
                        (((qrow * 128) | (dg * 32) | qbyt) ^ ((qrow & 7) << 4)));
                    ldsm4t(vh, uVH + voff);
                    ldsm4t(vl, uVL + voff);
                    mma16816(OD[2*dg],   phi, vh[0], vh[1]);
                    mma16816(OD[2*dg+1], phi, vh[2], vh[3]);
                    mma16816(OD[2*dg],   phi, vl[0], vl[1]);
                    mma16816(OD[2*dg+1], phi, vl[2], vl[3]);
                    mma16816(OD[2*dg],   plo, vh[0], vh[1]);
                    mma16816(OD[2*dg+1], plo, vh[2], vh[3]);
                }
            }
        }
    }

    // ---- row sums: quad-reduce (lanes in a quad share rows) ----
    rs0 += __shfl_xor_sync(0xffffffffu, rs0, 1);
    rs0 += __shfl_xor_sync(0xffffffffu, rs0, 2);
    rs1 += __shfl_xor_sync(0xffffffffu, rs1, 1);
    rs1 += __shfl_xor_sync(0xffffffffu, rs1, 2);
    const float inv0 = 1.0f / rs0, inv1 = 1.0f / rs1;

    // ---- output: scale PV accumulators ----
    float* o0 = out + (size_t)(bq + w * 16 + g) * DD;
    float* o1 = o0 + (size_t)8 * DD;
#pragma unroll
    for (int dn = 0; dn < 8; dn++) {
        *(float2*)(o0 + dn * 8 + t2 * 2) = make_float2(OD[dn][0] * inv0, OD[dn][1] * inv0);
        *(float2*)(o1 + dn * 8 + t2 * 2) = make_float2(OD[dn][2] * inv1, OD[dn][3] * inv1);
    }

    // ---- fused attn normalization: each quad rescales its own two rows ----
    float4* r0p = (float4*)(attn + (size_t)(bq + w * 16 + g) * SS);
    float4* r1p = (float4*)(attn + (size_t)(bq + w * 16 + 8 + g) * SS);
#pragma unroll 4
    for (int j4 = t2; j4 < SS / 4; j4 += 4) {
        float4 a = r0p[j4];
        a.x *= inv0; a.y *= inv0; a.z *= inv0; a.w *= inv0;
        r0p[j4] = a;
        float4 c = r1p[j4];
        c.x *= inv1; c.y *= inv1; c.z *= inv1; c.w *= inv1;
        r1p[j4] = c;
    }
}

extern "C" void kernel_launch(void* const* d_in, const int* in_sizes, int n_in,
                              void* d_out, int out_size)
{
    const float* q = (const float*)d_in[0];
    const float* k = (const float*)d_in[1];
    const float* v = (const float*)d_in[2];
    const void*  mask = d_in[3];

    float* out  = (float*)d_out;
    float* attn = out + (size_t)BB * SS * DD;   // tuple order: (output, attn)

    cudaFuncSetAttribute(sdpa_mma_kernel,
                         cudaFuncAttributeMaxDynamicSharedMemorySize, SMEM_DYN);

    dim3 grid(SS / TQ, BB);
    sdpa_mma_kernel<<<grid, NT, SMEM_DYN>>>(q, k, v, mask, out, attn);
}